// round 14
// baseline (speedup 1.0000x reference)
#include <cuda_runtime.h>
#include <math_constants.h>

#define NN   100000
#define FF   128
#define HH   4
#define EE   3200000
#define QKC  1024
#define ZC   512              // H*F floats per node in Z
#define NBINS NN              // one bin per row
#define NB2  ((NBINS + 1023) / 1024)   // 98
#define SMAX 96               // per-row smem capacity (P(cnt>96) ~ 1e-15)

// ---------------- device scratch (allocation-free) ----------------
__device__ float g_z[(size_t)NN * ZC];        // Z'[r][h*128+e] = (M_h^T x_r)[e] + u_h[e]
__device__ float g_M[(size_t)ZC * FF];        // Mcat[h*128+e][d] = M_h[d][e]
__device__ float g_u[ZC];                     // u_h[e] at [h*128+e]
__device__ float g_ssc[(size_t)EE * HH];      // fallback exp-scores (cnt > SMAX only)
__device__ int2  g_sedge[EE];                 // sorted: {col, orig edge id}
__device__ int   g_cnt[NBINS];
__device__ int   g_start[NBINS];
__device__ int   g_cursor[NBINS];
__device__ int   g_bsum[1024];
__device__ int   g_is64;

// ---------------- edge dtype detect (parallel) ----------------
__global__ void detect_kernel(const void* __restrict__ ei) {
    int2 v = ((const int2*)ei)[threadIdx.x];          // 1024 threads
    int any = __syncthreads_or(v.y != 0);
    if (threadIdx.x == 0) g_is64 = any ? 0 : 1;
}
__device__ __forceinline__ int load_idx(const void* __restrict__ ei, size_t i, int is64) {
    if (is64) return (int)((const long long*)ei)[i];
    return ((const int*)ei)[i];
}

// ---------------- init ----------------
__global__ void init_kernel() {
    int i = blockIdx.x * blockDim.x + threadIdx.x;
    if (i < NBINS) g_cnt[i] = 0;
}

// ---------------- Mcat: M_h = Wq_h^T Wk_h, stored transposed ----------------
__global__ void mcat_kernel(const float* __restrict__ W) {
    __shared__ float As[32][68];
    __shared__ float Bs[32][68];
    int h  = blockIdx.z;
    int db = blockIdx.x * 64;
    int eb = blockIdx.y * 64;
    int tid = threadIdx.x;
    int ty = tid >> 4, tx = tid & 15;
    int lr = tid >> 4;
    int lc = (tid & 15) * 4;

    float acc[4][4];
    #pragma unroll
    for (int i = 0; i < 4; i++)
        #pragma unroll
        for (int j = 0; j < 4; j++) acc[i][j] = 0.0f;

    for (int ib = 0; ib < 128; ib += 32) {
        #pragma unroll
        for (int s = 0; s < 2; s++) {
            int i = lr + s * 16;
            float4 va = *(const float4*)(W + (size_t)(h * 256 + ib + i) * FF + db + lc);
            As[i][lc + 0] = va.x; As[i][lc + 1] = va.y;
            As[i][lc + 2] = va.z; As[i][lc + 3] = va.w;
            float4 vb = *(const float4*)(W + (size_t)(h * 256 + 128 + ib + i) * FF + eb + lc);
            Bs[i][lc + 0] = vb.x; Bs[i][lc + 1] = vb.y;
            Bs[i][lc + 2] = vb.z; Bs[i][lc + 3] = vb.w;
        }
        __syncthreads();
        #pragma unroll
        for (int i = 0; i < 32; i++) {
            float a[4], b[4];
            #pragma unroll
            for (int d = 0; d < 4; d++) a[d] = As[i][ty * 4 + d];
            #pragma unroll
            for (int e = 0; e < 4; e++) b[e] = Bs[i][tx * 4 + e];
            #pragma unroll
            for (int d = 0; d < 4; d++)
                #pragma unroll
                for (int e = 0; e < 4; e++)
                    acc[d][e] += a[d] * b[e];
        }
        __syncthreads();
    }
    #pragma unroll
    for (int e = 0; e < 4; e++)
        #pragma unroll
        for (int d = 0; d < 4; d++)
            g_M[(size_t)(h * 128 + eb + tx * 4 + e) * FF + db + ty * 4 + d] = acc[d][e];
}

// ---------------- u_h[e] = sum_i b[h*256+i] * W[h*256+128+i][e] ----------------
__global__ void u_kernel(const float* __restrict__ W, const float* __restrict__ b) {
    int g = blockIdx.x * blockDim.x + threadIdx.x;
    if (g >= ZC) return;
    int h = g >> 7, e = g & 127;
    float s = 0.0f;
    for (int i = 0; i < 128; i++)
        s += b[h * 256 + i] * W[(size_t)(h * 256 + 128 + i) * FF + e];
    g_u[g] = s;
}

// ---------------- Z GEMM: Z' = x @ Mcat^T + u  (double-buffered, proven) ----------------
#define BM 128
#define BN 64
#define BK 16

__global__ void zgemm_kernel(const float* __restrict__ x) {
    __shared__ float As[2][BK][BM + 4];
    __shared__ float Bs[2][BK][BN + 4];

    int tid = threadIdx.x;
    int nb = blockIdx.x * BM;
    int jb = blockIdx.y * BN;

    int ar = tid >> 2;
    int ac = (tid & 3) * 4;
    int rb = tid >> 2;
    int cb = (tid & 3) * 4;

    int ty = tid >> 4;
    int tx = tid & 15;

    float acc[8][4];
    #pragma unroll
    for (int i = 0; i < 8; i++)
        #pragma unroll
        for (int j = 0; j < 4; j++) acc[i][j] = 0.0f;

    int gr0 = nb + ar, gr1 = nb + ar + 64;
    const float* xp0 = x + (size_t)gr0 * FF + ac;
    const float* xp1 = x + (size_t)gr1 * FF + ac;
    const float* mp  = g_M + (size_t)(jb + rb) * FF + cb;

    float4 va0 = (gr0 < NN) ? *(const float4*)xp0 : make_float4(0.f, 0.f, 0.f, 0.f);
    float4 va1 = (gr1 < NN) ? *(const float4*)xp1 : make_float4(0.f, 0.f, 0.f, 0.f);
    float4 vb  = *(const float4*)mp;
    As[0][ac + 0][ar] = va0.x; As[0][ac + 1][ar] = va0.y;
    As[0][ac + 2][ar] = va0.z; As[0][ac + 3][ar] = va0.w;
    As[0][ac + 0][ar + 64] = va1.x; As[0][ac + 1][ar + 64] = va1.y;
    As[0][ac + 2][ar + 64] = va1.z; As[0][ac + 3][ar + 64] = va1.w;
    Bs[0][cb + 0][rb] = vb.x; Bs[0][cb + 1][rb] = vb.y;
    Bs[0][cb + 2][rb] = vb.z; Bs[0][cb + 3][rb] = vb.w;
    __syncthreads();

    #pragma unroll
    for (int it = 0; it < FF / BK; it++) {
        int cur = it & 1;
        if (it < FF / BK - 1) {
            int kb = (it + 1) * BK;
            va0 = (gr0 < NN) ? *(const float4*)(xp0 + kb) : make_float4(0.f, 0.f, 0.f, 0.f);
            va1 = (gr1 < NN) ? *(const float4*)(xp1 + kb) : make_float4(0.f, 0.f, 0.f, 0.f);
            vb  = *(const float4*)(mp + kb);
        }
        #pragma unroll
        for (int k = 0; k < BK; k++) {
            float4 a0 = *(const float4*)&As[cur][k][ty * 8];
            float4 a1 = *(const float4*)&As[cur][k][ty * 8 + 4];
            float4 b  = *(const float4*)&Bs[cur][k][tx * 4];
            float a[8] = {a0.x, a0.y, a0.z, a0.w, a1.x, a1.y, a1.z, a1.w};
            float bb[4] = {b.x, b.y, b.z, b.w};
            #pragma unroll
            for (int i = 0; i < 8; i++)
                #pragma unroll
                for (int j = 0; j < 4; j++)
                    acc[i][j] += a[i] * bb[j];
        }
        if (it < FF / BK - 1) {
            int nxt = cur ^ 1;
            As[nxt][ac + 0][ar] = va0.x; As[nxt][ac + 1][ar] = va0.y;
            As[nxt][ac + 2][ar] = va0.z; As[nxt][ac + 3][ar] = va0.w;
            As[nxt][ac + 0][ar + 64] = va1.x; As[nxt][ac + 1][ar + 64] = va1.y;
            As[nxt][ac + 2][ar + 64] = va1.z; As[nxt][ac + 3][ar + 64] = va1.w;
            Bs[nxt][cb + 0][rb] = vb.x; Bs[nxt][cb + 1][rb] = vb.y;
            Bs[nxt][cb + 2][rb] = vb.z; Bs[nxt][cb + 3][rb] = vb.w;
            __syncthreads();
        }
    }

    float4 uv = *(const float4*)(g_u + jb + tx * 4);
    #pragma unroll
    for (int i = 0; i < 8; i++) {
        int gr = nb + ty * 8 + i;
        if (gr < NN) {
            float4 v = make_float4(acc[i][0] + uv.x, acc[i][1] + uv.y,
                                   acc[i][2] + uv.z, acc[i][3] + uv.w);
            *(float4*)(g_z + (size_t)gr * ZC + jb + tx * 4) = v;
        }
    }
}

// ---------------- counting sort of edges by row ----------------
__global__ void hist_kernel(const void* __restrict__ ei) {
    int e = blockIdx.x * blockDim.x + threadIdx.x;
    if (e >= EE) return;
    int row = load_idx(ei, e, g_is64);
    if ((unsigned)row >= NN) return;
    atomicAdd(&g_cnt[row], 1);
}

__global__ void scan1_kernel() {
    __shared__ int sm[1024];
    int tid = threadIdx.x;
    int i = blockIdx.x * 1024 + tid;
    int val = (i < NBINS) ? g_cnt[i] : 0;
    sm[tid] = val;
    __syncthreads();
    #pragma unroll
    for (int o = 1; o < 1024; o <<= 1) {
        int t = (tid >= o) ? sm[tid - o] : 0;
        __syncthreads();
        sm[tid] += t;
        __syncthreads();
    }
    if (i < NBINS) g_start[i] = sm[tid] - val;
    if (tid == 1023) g_bsum[blockIdx.x] = sm[tid];
}

__global__ void scan2_kernel() {   // single block, 128 threads (NB2=98)
    __shared__ int sm[128];
    int tid = threadIdx.x;
    int val = (tid < NB2) ? g_bsum[tid] : 0;
    sm[tid] = val;
    __syncthreads();
    #pragma unroll
    for (int o = 1; o < 128; o <<= 1) {
        int t = (tid >= o) ? sm[tid - o] : 0;
        __syncthreads();
        sm[tid] += t;
        __syncthreads();
    }
    if (tid < NB2) g_bsum[tid] = sm[tid] - val;
}

__global__ void scan3_kernel() {
    int i = blockIdx.x * blockDim.x + threadIdx.x;
    if (i >= NBINS) return;
    int s = g_start[i] + g_bsum[i >> 10];
    g_start[i] = s;
    g_cursor[i] = s;
}

__global__ void scatter_kernel(const void* __restrict__ ei) {
    int e = blockIdx.x * blockDim.x + threadIdx.x;
    if (e >= EE) return;
    int is64 = g_is64;
    int row = load_idx(ei, e, is64);
    int col = load_idx(ei, (size_t)EE + e, is64);
    if ((unsigned)row >= NN || (unsigned)col >= NN) return;
    int pos = atomicAdd(&g_cursor[row], 1);
    if ((unsigned)pos >= EE) return;
    g_sedge[pos] = make_int2(col, e);
}

// ---------------- fused score + softmax: warp per row ----------------
// sedge prefetched to smem (kills the col->x dependent chain);
// 4-edge unroll (16 LDG.128/lane in flight); exp-sum in-flight; pass 2 normalizes.
__global__ void score_kernel(const float* __restrict__ x, float* __restrict__ out) {
    __shared__ float ssm[8][SMAX * 4];   // per-warp exp-score staging
    __shared__ int2  sedg[8][SMAX];      // per-warp edge staging
    int wid = threadIdx.x >> 5;
    int row = (blockIdx.x * blockDim.x + threadIdx.x) >> 5;
    int lane = threadIdx.x & 31;
    if (row >= NN) return;
    int cnt = g_cnt[row];
    if (cnt == 0) return;
    int beg = g_start[row];
    bool use_sm = (cnt <= SMAX);

    int h = lane >> 3;                 // head 0..3
    int l = lane & 7;                  // sublane 0..7

    const float4* zr = (const float4*)(g_z + (size_t)row * ZC);
    int zi = h * 32 + l * 4;
    float4 q0 = zr[zi + 0], q1 = zr[zi + 1], q2 = zr[zi + 2], q3 = zr[zi + 3];

    if (use_sm) {
        for (int k = lane; k < cnt; k += 32) sedg[wid][k] = g_sedge[beg + k];
    }
    __syncwarp();

    float sum = 0.0f;                  // valid at l==0 (per-head partial)
    int j = 0;

    if (use_sm) {
        for (; j + 4 <= cnt; j += 4) {
            int c0 = sedg[wid][j].x,     c1 = sedg[wid][j + 1].x;
            int c2 = sedg[wid][j + 2].x, c3 = sedg[wid][j + 3].x;
            const float4* x0 = (const float4*)(x + (size_t)c0 * FF) + l * 4;
            const float4* x1 = (const float4*)(x + (size_t)c1 * FF) + l * 4;
            const float4* x2 = (const float4*)(x + (size_t)c2 * FF) + l * 4;
            const float4* x3 = (const float4*)(x + (size_t)c3 * FF) + l * 4;
            // batch all 16 loads (independent -> MLP 16)
            float4 a0 = x0[0], a1 = x0[1], a2 = x0[2], a3 = x0[3];
            float4 b0 = x1[0], b1 = x1[1], b2 = x1[2], b3 = x1[3];
            float4 d0 = x2[0], d1 = x2[1], d2 = x2[2], d3 = x2[3];
            float4 e0 = x3[0], e1 = x3[1], e2 = x3[2], e3 = x3[3];
            float s0 = q0.x*a0.x + q0.y*a0.y + q0.z*a0.z + q0.w*a0.w
                     + q1.x*a1.x + q1.y*a1.y + q1.z*a1.z + q1.w*a1.w
                     + q2.x*a2.x + q2.y*a2.y + q2.z*a2.z + q2.w*a2.w
                     + q3.x*a3.x + q3.y*a3.y + q3.z*a3.z + q3.w*a3.w;
            float s1 = q0.x*b0.x + q0.y*b0.y + q0.z*b0.z + q0.w*b0.w
                     + q1.x*b1.x + q1.y*b1.y + q1.z*b1.z + q1.w*b1.w
                     + q2.x*b2.x + q2.y*b2.y + q2.z*b2.z + q2.w*b2.w
                     + q3.x*b3.x + q3.y*b3.y + q3.z*b3.z + q3.w*b3.w;
            float s2 = q0.x*d0.x + q0.y*d0.y + q0.z*d0.z + q0.w*d0.w
                     + q1.x*d1.x + q1.y*d1.y + q1.z*d1.z + q1.w*d1.w
                     + q2.x*d2.x + q2.y*d2.y + q2.z*d2.z + q2.w*d2.w
                     + q3.x*d3.x + q3.y*d3.y + q3.z*d3.z + q3.w*d3.w;
            float s3 = q0.x*e0.x + q0.y*e0.y + q0.z*e0.z + q0.w*e0.w
                     + q1.x*e1.x + q1.y*e1.y + q1.z*e1.z + q1.w*e1.w
                     + q2.x*e2.x + q2.y*e2.y + q2.z*e2.z + q2.w*e2.w
                     + q3.x*e3.x + q3.y*e3.y + q3.z*e3.z + q3.w*e3.w;
            #pragma unroll
            for (int o = 1; o <= 4; o <<= 1) {
                s0 += __shfl_xor_sync(0xffffffffu, s0, o);
                s1 += __shfl_xor_sync(0xffffffffu, s1, o);
                s2 += __shfl_xor_sync(0xffffffffu, s2, o);
                s3 += __shfl_xor_sync(0xffffffffu, s3, o);
            }
            if (l == 0) {
                float ex0 = __expf(s0), ex1 = __expf(s1);
                float ex2 = __expf(s2), ex3 = __expf(s3);
                ssm[wid][(j + 0) * 4 + h] = ex0;
                ssm[wid][(j + 1) * 4 + h] = ex1;
                ssm[wid][(j + 2) * 4 + h] = ex2;
                ssm[wid][(j + 3) * 4 + h] = ex3;
                sum += (ex0 + ex1) + (ex2 + ex3);
            }
        }
        for (; j < cnt; j++) {
            int c0 = sedg[wid][j].x;
            const float4* x0 = (const float4*)(x + (size_t)c0 * FF) + l * 4;
            float4 a0 = x0[0], a1 = x0[1], a2 = x0[2], a3 = x0[3];
            float s0 = q0.x*a0.x + q0.y*a0.y + q0.z*a0.z + q0.w*a0.w
                     + q1.x*a1.x + q1.y*a1.y + q1.z*a1.z + q1.w*a1.w
                     + q2.x*a2.x + q2.y*a2.y + q2.z*a2.z + q2.w*a2.w
                     + q3.x*a3.x + q3.y*a3.y + q3.z*a3.z + q3.w*a3.w;
            #pragma unroll
            for (int o = 1; o <= 4; o <<= 1) s0 += __shfl_xor_sync(0xffffffffu, s0, o);
            if (l == 0) {
                float ex0 = __expf(s0);
                ssm[wid][j * 4 + h] = ex0;
                sum += ex0;
            }
        }
    } else {
        // rare fallback: global sedge + global ssc (exact, unoptimized)
        for (; j < cnt; j++) {
            int c0 = g_sedge[beg + j].x;
            const float4* x0 = (const float4*)(x + (size_t)c0 * FF) + l * 4;
            float4 a0 = x0[0], a1 = x0[1], a2 = x0[2], a3 = x0[3];
            float s0 = q0.x*a0.x + q0.y*a0.y + q0.z*a0.z + q0.w*a0.w
                     + q1.x*a1.x + q1.y*a1.y + q1.z*a1.z + q1.w*a1.w
                     + q2.x*a2.x + q2.y*a2.y + q2.z*a2.z + q2.w*a2.w
                     + q3.x*a3.x + q3.y*a3.y + q3.z*a3.z + q3.w*a3.w;
            #pragma unroll
            for (int o = 1; o <= 4; o <<= 1) s0 += __shfl_xor_sync(0xffffffffu, s0, o);
            if (l == 0) {
                float ex0 = __expf(s0);
                g_ssc[(size_t)(beg + j) * HH + h] = ex0;
                sum += ex0;
            }
        }
    }
    __syncwarp();

    float sm0 = __shfl_sync(0xffffffffu, sum, 0);
    float sm1 = __shfl_sync(0xffffffffu, sum, 8);
    float sm2 = __shfl_sync(0xffffffffu, sum, 16);
    float sm3 = __shfl_sync(0xffffffffu, sum, 24);
    float i0 = 1.0f / sm0, i1 = 1.0f / sm1, i2 = 1.0f / sm2, i3 = 1.0f / sm3;

    // pass 2: normalize + head-mean, scatter to original edge ids
    if (use_sm) {
        for (int k = lane; k < cnt; k += 32) {
            float4 e = *(const float4*)&ssm[wid][k * 4];
            int orig = sedg[wid][k].y;
            out[orig] = 0.25f * (e.x * i0 + e.y * i1 + e.z * i2 + e.w * i3);
        }
    } else {
        for (int k = lane; k < cnt; k += 32) {
            float4 e = *(const float4*)(g_ssc + (size_t)(beg + k) * HH);
            int orig = g_sedge[beg + k].y;
            out[orig] = 0.25f * (e.x * i0 + e.y * i1 + e.z * i2 + e.w * i3);
        }
    }
}

// ---------------- launch ----------------
extern "C" void kernel_launch(void* const* d_in, const int* in_sizes, int n_in,
                              void* d_out, int out_size) {
    const float* x    = nullptr;
    const float* W    = nullptr;
    const float* bias = nullptr;
    const void*  ei   = nullptr;
    for (int i = 0; i < n_in; i++) {
        long long sz = in_sizes[i];
        if      (sz == (long long)NN * FF)  x    = (const float*)d_in[i];
        else if (sz == (long long)QKC * FF) W    = (const float*)d_in[i];
        else if (sz == (long long)QKC)      bias = (const float*)d_in[i];
        else if (sz == 2LL * EE)            ei   = d_in[i];
    }
    if (!x)    x    = (const float*)d_in[0];
    if (!W)    W    = (const float*)d_in[1];
    if (!bias) bias = (const float*)d_in[2];
    if (!ei)   ei   = d_in[3];
    float* out = (float*)d_out;

    detect_kernel<<<1, 1024>>>(ei);                      // 1
    mcat_kernel<<<dim3(2, 2, 4), 256>>>(W);              // 2
    u_kernel<<<2, 256>>>(W, bias);                       // 3

    dim3 zgrid((NN + BM - 1) / BM, ZC / BN);
    zgemm_kernel<<<zgrid, 256>>>(x);                     // 4 <- ncu capture slot

    init_kernel<<<(NBINS + 255) / 256, 256>>>();         // 5
    hist_kernel<<<(EE + 255) / 256, 256>>>(ei);          // 6
    scan1_kernel<<<NB2, 1024>>>();
    scan2_kernel<<<1, 128>>>();
    scan3_kernel<<<(NBINS + 255) / 256, 256>>>();
    scatter_kernel<<<(EE + 255) / 256, 256>>>(ei);

    score_kernel<<<((size_t)NN * 32 + 255) / 256, 256>>>(x, out);
}

// round 15
// speedup vs baseline: 1.0014x; 1.0014x over previous
#include <cuda_runtime.h>
#include <math_constants.h>

#define NN   100000
#define FF   128
#define HH   4
#define EE   3200000
#define QKC  1024
#define ZC   512              // H*F floats per node in Z
#define NBINS NN              // one bin per row
#define NB2  ((NBINS + 1023) / 1024)   // 98
#define SMAX 96               // per-row smem capacity (P(cnt>96) ~ 1e-15)

// ---------------- device scratch (allocation-free) ----------------
__device__ float g_z[(size_t)NN * ZC];        // Z'[r][h*128+e] = (M_h^T x_r)[e] + u_h[e]
__device__ float g_M[(size_t)ZC * FF];        // Mcat[h*128+e][d] = M_h[d][e]
__device__ float g_u[ZC];                     // u_h[e] at [h*128+e]
__device__ float g_ssc[(size_t)EE * HH];      // fallback exp-scores (cnt > SMAX only)
__device__ int2  g_sedge[EE];                 // sorted: {col, orig edge id}
__device__ int   g_cnt[NBINS];
__device__ int   g_start[NBINS];
__device__ int   g_cursor[NBINS];
__device__ int   g_bsum[1024];
__device__ int   g_is64;

// ---------------- edge dtype detect (parallel) ----------------
__global__ void detect_kernel(const void* __restrict__ ei) {
    int2 v = ((const int2*)ei)[threadIdx.x];          // 1024 threads
    int any = __syncthreads_or(v.y != 0);
    if (threadIdx.x == 0) g_is64 = any ? 0 : 1;
}
// streaming loads: edge list is single-use in every kernel that reads it
__device__ __forceinline__ int load_idx_cs(const void* __restrict__ ei, size_t i, int is64) {
    if (is64) return (int)__ldcs((const long long*)ei + i);
    return __ldcs((const int*)ei + i);
}

// ---------------- init ----------------
__global__ void init_kernel() {
    int i = blockIdx.x * blockDim.x + threadIdx.x;
    if (i < NBINS) g_cnt[i] = 0;
}

// ---------------- Mcat: M_h = Wq_h^T Wk_h, stored transposed ----------------
__global__ void mcat_kernel(const float* __restrict__ W) {
    __shared__ float As[32][68];
    __shared__ float Bs[32][68];
    int h  = blockIdx.z;
    int db = blockIdx.x * 64;
    int eb = blockIdx.y * 64;
    int tid = threadIdx.x;
    int ty = tid >> 4, tx = tid & 15;
    int lr = tid >> 4;
    int lc = (tid & 15) * 4;

    float acc[4][4];
    #pragma unroll
    for (int i = 0; i < 4; i++)
        #pragma unroll
        for (int j = 0; j < 4; j++) acc[i][j] = 0.0f;

    for (int ib = 0; ib < 128; ib += 32) {
        #pragma unroll
        for (int s = 0; s < 2; s++) {
            int i = lr + s * 16;
            float4 va = *(const float4*)(W + (size_t)(h * 256 + ib + i) * FF + db + lc);
            As[i][lc + 0] = va.x; As[i][lc + 1] = va.y;
            As[i][lc + 2] = va.z; As[i][lc + 3] = va.w;
            float4 vb = *(const float4*)(W + (size_t)(h * 256 + 128 + ib + i) * FF + eb + lc);
            Bs[i][lc + 0] = vb.x; Bs[i][lc + 1] = vb.y;
            Bs[i][lc + 2] = vb.z; Bs[i][lc + 3] = vb.w;
        }
        __syncthreads();
        #pragma unroll
        for (int i = 0; i < 32; i++) {
            float a[4], b[4];
            #pragma unroll
            for (int d = 0; d < 4; d++) a[d] = As[i][ty * 4 + d];
            #pragma unroll
            for (int e = 0; e < 4; e++) b[e] = Bs[i][tx * 4 + e];
            #pragma unroll
            for (int d = 0; d < 4; d++)
                #pragma unroll
                for (int e = 0; e < 4; e++)
                    acc[d][e] += a[d] * b[e];
        }
        __syncthreads();
    }
    #pragma unroll
    for (int e = 0; e < 4; e++)
        #pragma unroll
        for (int d = 0; d < 4; d++)
            g_M[(size_t)(h * 128 + eb + tx * 4 + e) * FF + db + ty * 4 + d] = acc[d][e];
}

// ---------------- u_h[e] = sum_i b[h*256+i] * W[h*256+128+i][e] ----------------
__global__ void u_kernel(const float* __restrict__ W, const float* __restrict__ b) {
    int g = blockIdx.x * blockDim.x + threadIdx.x;
    if (g >= ZC) return;
    int h = g >> 7, e = g & 127;
    float s = 0.0f;
    for (int i = 0; i < 128; i++)
        s += b[h * 256 + i] * W[(size_t)(h * 256 + 128 + i) * FF + e];
    g_u[g] = s;
}

// ---------------- Z GEMM: Z' = x @ Mcat^T + u  (double-buffered, proven) ----------------
#define BM 128
#define BN 64
#define BK 16

__global__ void zgemm_kernel(const float* __restrict__ x) {
    __shared__ float As[2][BK][BM + 4];
    __shared__ float Bs[2][BK][BN + 4];

    int tid = threadIdx.x;
    int nb = blockIdx.x * BM;
    int jb = blockIdx.y * BN;

    int ar = tid >> 2;
    int ac = (tid & 3) * 4;
    int rb = tid >> 2;
    int cb = (tid & 3) * 4;

    int ty = tid >> 4;
    int tx = tid & 15;

    float acc[8][4];
    #pragma unroll
    for (int i = 0; i < 8; i++)
        #pragma unroll
        for (int j = 0; j < 4; j++) acc[i][j] = 0.0f;

    int gr0 = nb + ar, gr1 = nb + ar + 64;
    const float* xp0 = x + (size_t)gr0 * FF + ac;
    const float* xp1 = x + (size_t)gr1 * FF + ac;
    const float* mp  = g_M + (size_t)(jb + rb) * FF + cb;

    float4 va0 = (gr0 < NN) ? *(const float4*)xp0 : make_float4(0.f, 0.f, 0.f, 0.f);
    float4 va1 = (gr1 < NN) ? *(const float4*)xp1 : make_float4(0.f, 0.f, 0.f, 0.f);
    float4 vb  = *(const float4*)mp;
    As[0][ac + 0][ar] = va0.x; As[0][ac + 1][ar] = va0.y;
    As[0][ac + 2][ar] = va0.z; As[0][ac + 3][ar] = va0.w;
    As[0][ac + 0][ar + 64] = va1.x; As[0][ac + 1][ar + 64] = va1.y;
    As[0][ac + 2][ar + 64] = va1.z; As[0][ac + 3][ar + 64] = va1.w;
    Bs[0][cb + 0][rb] = vb.x; Bs[0][cb + 1][rb] = vb.y;
    Bs[0][cb + 2][rb] = vb.z; Bs[0][cb + 3][rb] = vb.w;
    __syncthreads();

    #pragma unroll
    for (int it = 0; it < FF / BK; it++) {
        int cur = it & 1;
        if (it < FF / BK - 1) {
            int kb = (it + 1) * BK;
            va0 = (gr0 < NN) ? *(const float4*)(xp0 + kb) : make_float4(0.f, 0.f, 0.f, 0.f);
            va1 = (gr1 < NN) ? *(const float4*)(xp1 + kb) : make_float4(0.f, 0.f, 0.f, 0.f);
            vb  = *(const float4*)(mp + kb);
        }
        #pragma unroll
        for (int k = 0; k < BK; k++) {
            float4 a0 = *(const float4*)&As[cur][k][ty * 8];
            float4 a1 = *(const float4*)&As[cur][k][ty * 8 + 4];
            float4 b  = *(const float4*)&Bs[cur][k][tx * 4];
            float a[8] = {a0.x, a0.y, a0.z, a0.w, a1.x, a1.y, a1.z, a1.w};
            float bb[4] = {b.x, b.y, b.z, b.w};
            #pragma unroll
            for (int i = 0; i < 8; i++)
                #pragma unroll
                for (int j = 0; j < 4; j++)
                    acc[i][j] += a[i] * bb[j];
        }
        if (it < FF / BK - 1) {
            int nxt = cur ^ 1;
            As[nxt][ac + 0][ar] = va0.x; As[nxt][ac + 1][ar] = va0.y;
            As[nxt][ac + 2][ar] = va0.z; As[nxt][ac + 3][ar] = va0.w;
            As[nxt][ac + 0][ar + 64] = va1.x; As[nxt][ac + 1][ar + 64] = va1.y;
            As[nxt][ac + 2][ar + 64] = va1.z; As[nxt][ac + 3][ar + 64] = va1.w;
            Bs[nxt][cb + 0][rb] = vb.x; Bs[nxt][cb + 1][rb] = vb.y;
            Bs[nxt][cb + 2][rb] = vb.z; Bs[nxt][cb + 3][rb] = vb.w;
            __syncthreads();
        }
    }

    // epilogue: add u; store with evict-first (z is single-use, read once in score)
    float4 uv = *(const float4*)(g_u + jb + tx * 4);
    #pragma unroll
    for (int i = 0; i < 8; i++) {
        int gr = nb + ty * 8 + i;
        if (gr < NN) {
            float4 v = make_float4(acc[i][0] + uv.x, acc[i][1] + uv.y,
                                   acc[i][2] + uv.z, acc[i][3] + uv.w);
            __stcs((float4*)(g_z + (size_t)gr * ZC + jb + tx * 4), v);
        }
    }
}

// ---------------- counting sort of edges by row ----------------
__global__ void hist_kernel(const void* __restrict__ ei) {
    int e = blockIdx.x * blockDim.x + threadIdx.x;
    if (e >= EE) return;
    int row = load_idx_cs(ei, e, g_is64);
    if ((unsigned)row >= NN) return;
    atomicAdd(&g_cnt[row], 1);
}

__global__ void scan1_kernel() {
    __shared__ int sm[1024];
    int tid = threadIdx.x;
    int i = blockIdx.x * 1024 + tid;
    int val = (i < NBINS) ? g_cnt[i] : 0;
    sm[tid] = val;
    __syncthreads();
    #pragma unroll
    for (int o = 1; o < 1024; o <<= 1) {
        int t = (tid >= o) ? sm[tid - o] : 0;
        __syncthreads();
        sm[tid] += t;
        __syncthreads();
    }
    if (i < NBINS) g_start[i] = sm[tid] - val;
    if (tid == 1023) g_bsum[blockIdx.x] = sm[tid];
}

__global__ void scan2_kernel() {   // single block, 128 threads (NB2=98)
    __shared__ int sm[128];
    int tid = threadIdx.x;
    int val = (tid < NB2) ? g_bsum[tid] : 0;
    sm[tid] = val;
    __syncthreads();
    #pragma unroll
    for (int o = 1; o < 128; o <<= 1) {
        int t = (tid >= o) ? sm[tid - o] : 0;
        __syncthreads();
        sm[tid] += t;
        __syncthreads();
    }
    if (tid < NB2) g_bsum[tid] = sm[tid] - val;
}

__global__ void scan3_kernel() {
    int i = blockIdx.x * blockDim.x + threadIdx.x;
    if (i >= NBINS) return;
    int s = g_start[i] + g_bsum[i >> 10];
    g_start[i] = s;
    g_cursor[i] = s;
}

__global__ void scatter_kernel(const void* __restrict__ ei) {
    int e = blockIdx.x * blockDim.x + threadIdx.x;
    if (e >= EE) return;
    int is64 = g_is64;
    int row = load_idx_cs(ei, e, is64);
    int col = load_idx_cs(ei, (size_t)EE + e, is64);
    if ((unsigned)row >= NN || (unsigned)col >= NN) return;
    int pos = atomicAdd(&g_cursor[row], 1);
    if ((unsigned)pos >= EE) return;
    __stcs(&g_sedge[pos], make_int2(col, e));   // single-use until score reads it
}

// ---------------- fused score + softmax: warp per row ----------------
// All single-use streams (z row, sedge, out) use evict-first policy so the
// 51MB x table stays L2-resident for the random gathers.
__global__ void score_kernel(const float* __restrict__ x, float* __restrict__ out) {
    __shared__ float ssm[8][SMAX * 4];   // per-warp exp-score staging
    __shared__ int2  sedg[8][SMAX];      // per-warp edge staging
    int wid = threadIdx.x >> 5;
    int row = (blockIdx.x * blockDim.x + threadIdx.x) >> 5;
    int lane = threadIdx.x & 31;
    if (row >= NN) return;
    int cnt = g_cnt[row];
    if (cnt == 0) return;
    int beg = g_start[row];
    bool use_sm = (cnt <= SMAX);

    int h = lane >> 3;                 // head 0..3
    int l = lane & 7;                  // sublane 0..7

    const float4* zr = (const float4*)(g_z + (size_t)row * ZC);
    int zi = h * 32 + l * 4;
    float4 q0 = __ldcs(zr + zi + 0), q1 = __ldcs(zr + zi + 1);
    float4 q2 = __ldcs(zr + zi + 2), q3 = __ldcs(zr + zi + 3);

    if (use_sm) {
        for (int k = lane; k < cnt; k += 32) sedg[wid][k] = __ldcs(&g_sedge[beg + k]);
    }
    __syncwarp();

    float sum = 0.0f;                  // valid at l==0 (per-head partial)
    int j = 0;

    if (use_sm) {
        for (; j + 4 <= cnt; j += 4) {
            int c0 = sedg[wid][j].x,     c1 = sedg[wid][j + 1].x;
            int c2 = sedg[wid][j + 2].x, c3 = sedg[wid][j + 3].x;
            const float4* x0 = (const float4*)(x + (size_t)c0 * FF) + l * 4;
            const float4* x1 = (const float4*)(x + (size_t)c1 * FF) + l * 4;
            const float4* x2 = (const float4*)(x + (size_t)c2 * FF) + l * 4;
            const float4* x3 = (const float4*)(x + (size_t)c3 * FF) + l * 4;
            float4 a0 = x0[0], a1 = x0[1], a2 = x0[2], a3 = x0[3];
            float4 b0 = x1[0], b1 = x1[1], b2 = x1[2], b3 = x1[3];
            float4 d0 = x2[0], d1 = x2[1], d2 = x2[2], d3 = x2[3];
            float4 e0 = x3[0], e1 = x3[1], e2 = x3[2], e3 = x3[3];
            float s0 = q0.x*a0.x + q0.y*a0.y + q0.z*a0.z + q0.w*a0.w
                     + q1.x*a1.x + q1.y*a1.y + q1.z*a1.z + q1.w*a1.w
                     + q2.x*a2.x + q2.y*a2.y + q2.z*a2.z + q2.w*a2.w
                     + q3.x*a3.x + q3.y*a3.y + q3.z*a3.z + q3.w*a3.w;
            float s1 = q0.x*b0.x + q0.y*b0.y + q0.z*b0.z + q0.w*b0.w
                     + q1.x*b1.x + q1.y*b1.y + q1.z*b1.z + q1.w*b1.w
                     + q2.x*b2.x + q2.y*b2.y + q2.z*b2.z + q2.w*b2.w
                     + q3.x*b3.x + q3.y*b3.y + q3.z*b3.z + q3.w*b3.w;
            float s2 = q0.x*d0.x + q0.y*d0.y + q0.z*d0.z + q0.w*d0.w
                     + q1.x*d1.x + q1.y*d1.y + q1.z*d1.z + q1.w*d1.w
                     + q2.x*d2.x + q2.y*d2.y + q2.z*d2.z + q2.w*d2.w
                     + q3.x*d3.x + q3.y*d3.y + q3.z*d3.z + q3.w*d3.w;
            float s3 = q0.x*e0.x + q0.y*e0.y + q0.z*e0.z + q0.w*e0.w
                     + q1.x*e1.x + q1.y*e1.y + q1.z*e1.z + q1.w*e1.w
                     + q2.x*e2.x + q2.y*e2.y + q2.z*e2.z + q2.w*e2.w
                     + q3.x*e3.x + q3.y*e3.y + q3.z*e3.z + q3.w*e3.w;
            #pragma unroll
            for (int o = 1; o <= 4; o <<= 1) {
                s0 += __shfl_xor_sync(0xffffffffu, s0, o);
                s1 += __shfl_xor_sync(0xffffffffu, s1, o);
                s2 += __shfl_xor_sync(0xffffffffu, s2, o);
                s3 += __shfl_xor_sync(0xffffffffu, s3, o);
            }
            if (l == 0) {
                float ex0 = __expf(s0), ex1 = __expf(s1);
                float ex2 = __expf(s2), ex3 = __expf(s3);
                ssm[wid][(j + 0) * 4 + h] = ex0;
                ssm[wid][(j + 1) * 4 + h] = ex1;
                ssm[wid][(j + 2) * 4 + h] = ex2;
                ssm[wid][(j + 3) * 4 + h] = ex3;
                sum += (ex0 + ex1) + (ex2 + ex3);
            }
        }
        for (; j < cnt; j++) {
            int c0 = sedg[wid][j].x;
            const float4* x0 = (const float4*)(x + (size_t)c0 * FF) + l * 4;
            float4 a0 = x0[0], a1 = x0[1], a2 = x0[2], a3 = x0[3];
            float s0 = q0.x*a0.x + q0.y*a0.y + q0.z*a0.z + q0.w*a0.w
                     + q1.x*a1.x + q1.y*a1.y + q1.z*a1.z + q1.w*a1.w
                     + q2.x*a2.x + q2.y*a2.y + q2.z*a2.z + q2.w*a2.w
                     + q3.x*a3.x + q3.y*a3.y + q3.z*a3.z + q3.w*a3.w;
            #pragma unroll
            for (int o = 1; o <= 4; o <<= 1) s0 += __shfl_xor_sync(0xffffffffu, s0, o);
            if (l == 0) {
                float ex0 = __expf(s0);
                ssm[wid][j * 4 + h] = ex0;
                sum += ex0;
            }
        }
    } else {
        // rare fallback: global sedge + global ssc (exact, unoptimized)
        for (; j < cnt; j++) {
            int2 se = __ldcs(&g_sedge[beg + j]);
            const float4* x0 = (const float4*)(x + (size_t)se.x * FF) + l * 4;
            float4 a0 = x0[0], a1 = x0[1], a2 = x0[2], a3 = x0[3];
            float s0 = q0.x*a0.x + q0.y*a0.y + q0.z*a0.z + q0.w*a0.w
                     + q1.x*a1.x + q1.y*a1.y + q1.z*a1.z + q1.w*a1.w
                     + q2.x*a2.x + q2.y*a2.y + q2.z*a2.z + q2.w*a2.w
                     + q3.x*a3.x + q3.y*a3.y + q3.z*a3.z + q3.w*a3.w;
            #pragma unroll
            for (int o = 1; o <= 4; o <<= 1) s0 += __shfl_xor_sync(0xffffffffu, s0, o);
            if (l == 0) {
                float ex0 = __expf(s0);
                g_ssc[(size_t)(beg + j) * HH + h] = ex0;
                sum += ex0;
            }
        }
    }
    __syncwarp();

    float sm0 = __shfl_sync(0xffffffffu, sum, 0);
    float sm1 = __shfl_sync(0xffffffffu, sum, 8);
    float sm2 = __shfl_sync(0xffffffffu, sum, 16);
    float sm3 = __shfl_sync(0xffffffffu, sum, 24);
    float i0 = 1.0f / sm0, i1 = 1.0f / sm1, i2 = 1.0f / sm2, i3 = 1.0f / sm3;

    // pass 2: normalize + head-mean; scatter with evict-first stores
    if (use_sm) {
        for (int k = lane; k < cnt; k += 32) {
            float4 e = *(const float4*)&ssm[wid][k * 4];
            int orig = sedg[wid][k].y;
            __stcs(&out[orig], 0.25f * (e.x * i0 + e.y * i1 + e.z * i2 + e.w * i3));
        }
    } else {
        for (int k = lane; k < cnt; k += 32) {
            float4 e = *(const float4*)(g_ssc + (size_t)(beg + k) * HH);
            int2 se = __ldcs(&g_sedge[beg + k]);
            __stcs(&out[se.y], 0.25f * (e.x * i0 + e.y * i1 + e.z * i2 + e.w * i3));
        }
    }
}

// ---------------- launch ----------------
extern "C" void kernel_launch(void* const* d_in, const int* in_sizes, int n_in,
                              void* d_out, int out_size) {
    const float* x    = nullptr;
    const float* W    = nullptr;
    const float* bias = nullptr;
    const void*  ei   = nullptr;
    for (int i = 0; i < n_in; i++) {
        long long sz = in_sizes[i];
        if      (sz == (long long)NN * FF)  x    = (const float*)d_in[i];
        else if (sz == (long long)QKC * FF) W    = (const float*)d_in[i];
        else if (sz == (long long)QKC)      bias = (const float*)d_in[i];
        else if (sz == 2LL * EE)            ei   = d_in[i];
    }
    if (!x)    x    = (const float*)d_in[0];
    if (!W)    W    = (const float*)d_in[1];
    if (!bias) bias = (const float*)d_in[2];
    if (!ei)   ei   = d_in[3];
    float* out = (float*)d_out;

    detect_kernel<<<1, 1024>>>(ei);                      // 1
    mcat_kernel<<<dim3(2, 2, 4), 256>>>(W);              // 2
    u_kernel<<<2, 256>>>(W, bias);                       // 3

    dim3 zgrid((NN + BM - 1) / BM, ZC / BN);
    zgemm_kernel<<<zgrid, 256>>>(x);                     // 4 <- ncu capture slot

    init_kernel<<<(NBINS + 255) / 256, 256>>>();         // 5
    hist_kernel<<<(EE + 255) / 256, 256>>>(ei);          // 6
    scan1_kernel<<<NB2, 1024>>>();
    scan2_kernel<<<1, 128>>>();
    scan3_kernel<<<(NBINS + 255) / 256, 256>>>();
    scatter_kernel<<<(EE + 255) / 256, 256>>>(ei);

    score_kernel<<<((size_t)NN * 32 + 255) / 256, 256>>>(x, out);
}

// round 16
// speedup vs baseline: 1.6729x; 1.6705x over previous
#include <cuda_runtime.h>
#include <math_constants.h>

#define NN   100000
#define FF   128
#define HH   4
#define EE   3200000
#define QKC  1024
#define ZC   512              // H*F floats per node in Z
#define NBINS NN              // one bin per row
#define NB2  ((NBINS + 1023) / 1024)   // 98
#define SMAX 96               // per-row smem capacity (P(cnt>96) ~ 1e-15)

// ---------------- device scratch (allocation-free) ----------------
__device__ float g_z[(size_t)NN * ZC];        // Z'[r][h*128+e] = (M_h^T x_r)[e] + u_h[e]
__device__ float g_M[(size_t)ZC * FF];        // Mcat[h*128+e][d] = M_h[d][e]
__device__ float g_u[ZC];                     // u_h[e] at [h*128+e]
__device__ float g_ssc[(size_t)EE * HH];      // fallback exp-scores (cnt > SMAX only)
__device__ int2  g_sedge[EE];                 // sorted: {col, orig edge id}
__device__ int   g_cnt[NBINS];
__device__ int   g_start[NBINS];
__device__ int   g_cursor[NBINS];
__device__ int   g_bsum[1024];
__device__ int   g_is64;

// ---------------- edge dtype detect (parallel) ----------------
__global__ void detect_kernel(const void* __restrict__ ei) {
    int2 v = ((const int2*)ei)[threadIdx.x];          // 1024 threads
    int any = __syncthreads_or(v.y != 0);
    if (threadIdx.x == 0) g_is64 = any ? 0 : 1;
}
__device__ __forceinline__ int load_idx_cs(const void* __restrict__ ei, size_t i, int is64) {
    if (is64) return (int)__ldcs((const long long*)ei + i);
    return __ldcs((const int*)ei + i);
}

// ---------------- init ----------------
__global__ void init_kernel() {
    int i = blockIdx.x * blockDim.x + threadIdx.x;
    if (i < NBINS) g_cnt[i] = 0;
}

// ---------------- Mcat: M_h = Wq_h^T Wk_h, stored transposed ----------------
__global__ void mcat_kernel(const float* __restrict__ W) {
    __shared__ float As[32][68];
    __shared__ float Bs[32][68];
    int h  = blockIdx.z;
    int db = blockIdx.x * 64;
    int eb = blockIdx.y * 64;
    int tid = threadIdx.x;
    int ty = tid >> 4, tx = tid & 15;
    int lr = tid >> 4;
    int lc = (tid & 15) * 4;

    float acc[4][4];
    #pragma unroll
    for (int i = 0; i < 4; i++)
        #pragma unroll
        for (int j = 0; j < 4; j++) acc[i][j] = 0.0f;

    for (int ib = 0; ib < 128; ib += 32) {
        #pragma unroll
        for (int s = 0; s < 2; s++) {
            int i = lr + s * 16;
            float4 va = *(const float4*)(W + (size_t)(h * 256 + ib + i) * FF + db + lc);
            As[i][lc + 0] = va.x; As[i][lc + 1] = va.y;
            As[i][lc + 2] = va.z; As[i][lc + 3] = va.w;
            float4 vb = *(const float4*)(W + (size_t)(h * 256 + 128 + ib + i) * FF + eb + lc);
            Bs[i][lc + 0] = vb.x; Bs[i][lc + 1] = vb.y;
            Bs[i][lc + 2] = vb.z; Bs[i][lc + 3] = vb.w;
        }
        __syncthreads();
        #pragma unroll
        for (int i = 0; i < 32; i++) {
            float a[4], b[4];
            #pragma unroll
            for (int d = 0; d < 4; d++) a[d] = As[i][ty * 4 + d];
            #pragma unroll
            for (int e = 0; e < 4; e++) b[e] = Bs[i][tx * 4 + e];
            #pragma unroll
            for (int d = 0; d < 4; d++)
                #pragma unroll
                for (int e = 0; e < 4; e++)
                    acc[d][e] += a[d] * b[e];
        }
        __syncthreads();
    }
    #pragma unroll
    for (int e = 0; e < 4; e++)
        #pragma unroll
        for (int d = 0; d < 4; d++)
            g_M[(size_t)(h * 128 + eb + tx * 4 + e) * FF + db + ty * 4 + d] = acc[d][e];
}

// ---------------- u_h[e] = sum_i b[h*256+i] * W[h*256+128+i][e] ----------------
__global__ void u_kernel(const float* __restrict__ W, const float* __restrict__ b) {
    int g = blockIdx.x * blockDim.x + threadIdx.x;
    if (g >= ZC) return;
    int h = g >> 7, e = g & 127;
    float s = 0.0f;
    for (int i = 0; i < 128; i++)
        s += b[h * 256 + i] * W[(size_t)(h * 256 + 128 + i) * FF + e];
    g_u[g] = s;
}

// ---------------- Z GEMM: Z' = x @ Mcat^T + u  (double-buffered, proven) ----------------
#define BM 128
#define BN 64
#define BK 16

__global__ void zgemm_kernel(const float* __restrict__ x) {
    __shared__ float As[2][BK][BM + 4];
    __shared__ float Bs[2][BK][BN + 4];

    int tid = threadIdx.x;
    int nb = blockIdx.x * BM;
    int jb = blockIdx.y * BN;

    int ar = tid >> 2;
    int ac = (tid & 3) * 4;
    int rb = tid >> 2;
    int cb = (tid & 3) * 4;

    int ty = tid >> 4;
    int tx = tid & 15;

    float acc[8][4];
    #pragma unroll
    for (int i = 0; i < 8; i++)
        #pragma unroll
        for (int j = 0; j < 4; j++) acc[i][j] = 0.0f;

    int gr0 = nb + ar, gr1 = nb + ar + 64;
    const float* xp0 = x + (size_t)gr0 * FF + ac;
    const float* xp1 = x + (size_t)gr1 * FF + ac;
    const float* mp  = g_M + (size_t)(jb + rb) * FF + cb;

    float4 va0 = (gr0 < NN) ? *(const float4*)xp0 : make_float4(0.f, 0.f, 0.f, 0.f);
    float4 va1 = (gr1 < NN) ? *(const float4*)xp1 : make_float4(0.f, 0.f, 0.f, 0.f);
    float4 vb  = *(const float4*)mp;
    As[0][ac + 0][ar] = va0.x; As[0][ac + 1][ar] = va0.y;
    As[0][ac + 2][ar] = va0.z; As[0][ac + 3][ar] = va0.w;
    As[0][ac + 0][ar + 64] = va1.x; As[0][ac + 1][ar + 64] = va1.y;
    As[0][ac + 2][ar + 64] = va1.z; As[0][ac + 3][ar + 64] = va1.w;
    Bs[0][cb + 0][rb] = vb.x; Bs[0][cb + 1][rb] = vb.y;
    Bs[0][cb + 2][rb] = vb.z; Bs[0][cb + 3][rb] = vb.w;
    __syncthreads();

    #pragma unroll
    for (int it = 0; it < FF / BK; it++) {
        int cur = it & 1;
        if (it < FF / BK - 1) {
            int kb = (it + 1) * BK;
            va0 = (gr0 < NN) ? *(const float4*)(xp0 + kb) : make_float4(0.f, 0.f, 0.f, 0.f);
            va1 = (gr1 < NN) ? *(const float4*)(xp1 + kb) : make_float4(0.f, 0.f, 0.f, 0.f);
            vb  = *(const float4*)(mp + kb);
        }
        #pragma unroll
        for (int k = 0; k < BK; k++) {
            float4 a0 = *(const float4*)&As[cur][k][ty * 8];
            float4 a1 = *(const float4*)&As[cur][k][ty * 8 + 4];
            float4 b  = *(const float4*)&Bs[cur][k][tx * 4];
            float a[8] = {a0.x, a0.y, a0.z, a0.w, a1.x, a1.y, a1.z, a1.w};
            float bb[4] = {b.x, b.y, b.z, b.w};
            #pragma unroll
            for (int i = 0; i < 8; i++)
                #pragma unroll
                for (int j = 0; j < 4; j++)
                    acc[i][j] += a[i] * bb[j];
        }
        if (it < FF / BK - 1) {
            int nxt = cur ^ 1;
            As[nxt][ac + 0][ar] = va0.x; As[nxt][ac + 1][ar] = va0.y;
            As[nxt][ac + 2][ar] = va0.z; As[nxt][ac + 3][ar] = va0.w;
            As[nxt][ac + 0][ar + 64] = va1.x; As[nxt][ac + 1][ar + 64] = va1.y;
            As[nxt][ac + 2][ar + 64] = va1.z; As[nxt][ac + 3][ar + 64] = va1.w;
            Bs[nxt][cb + 0][rb] = vb.x; Bs[nxt][cb + 1][rb] = vb.y;
            Bs[nxt][cb + 2][rb] = vb.z; Bs[nxt][cb + 3][rb] = vb.w;
            __syncthreads();
        }
    }

    // epilogue: add u; store with evict-first (z is single-use, read once in score)
    float4 uv = *(const float4*)(g_u + jb + tx * 4);
    #pragma unroll
    for (int i = 0; i < 8; i++) {
        int gr = nb + ty * 8 + i;
        if (gr < NN) {
            float4 v = make_float4(acc[i][0] + uv.x, acc[i][1] + uv.y,
                                   acc[i][2] + uv.z, acc[i][3] + uv.w);
            __stcs((float4*)(g_z + (size_t)gr * ZC + jb + tx * 4), v);
        }
    }
}

// ---------------- counting sort of edges by row ----------------
__global__ void hist_kernel(const void* __restrict__ ei) {
    int e = blockIdx.x * blockDim.x + threadIdx.x;
    if (e >= EE) return;
    int row = load_idx_cs(ei, e, g_is64);
    if ((unsigned)row >= NN) return;
    atomicAdd(&g_cnt[row], 1);
}

__global__ void scan1_kernel() {
    __shared__ int sm[1024];
    int tid = threadIdx.x;
    int i = blockIdx.x * 1024 + tid;
    int val = (i < NBINS) ? g_cnt[i] : 0;
    sm[tid] = val;
    __syncthreads();
    #pragma unroll
    for (int o = 1; o < 1024; o <<= 1) {
        int t = (tid >= o) ? sm[tid - o] : 0;
        __syncthreads();
        sm[tid] += t;
        __syncthreads();
    }
    if (i < NBINS) g_start[i] = sm[tid] - val;
    if (tid == 1023) g_bsum[blockIdx.x] = sm[tid];
}

__global__ void scan2_kernel() {   // single block, 128 threads (NB2=98)
    __shared__ int sm[128];
    int tid = threadIdx.x;
    int val = (tid < NB2) ? g_bsum[tid] : 0;
    sm[tid] = val;
    __syncthreads();
    #pragma unroll
    for (int o = 1; o < 128; o <<= 1) {
        int t = (tid >= o) ? sm[tid - o] : 0;
        __syncthreads();
        sm[tid] += t;
        __syncthreads();
    }
    if (tid < NB2) g_bsum[tid] = sm[tid] - val;
}

__global__ void scan3_kernel() {
    int i = blockIdx.x * blockDim.x + threadIdx.x;
    if (i >= NBINS) return;
    int s = g_start[i] + g_bsum[i >> 10];
    g_start[i] = s;
    g_cursor[i] = s;
}

__global__ void scatter_kernel(const void* __restrict__ ei) {
    int e = blockIdx.x * blockDim.x + threadIdx.x;
    if (e >= EE) return;
    int is64 = g_is64;
    int row = load_idx_cs(ei, e, is64);
    int col = load_idx_cs(ei, (size_t)EE + e, is64);
    if ((unsigned)row >= NN || (unsigned)col >= NN) return;
    int pos = atomicAdd(&g_cursor[row], 1);
    if ((unsigned)pos >= EE) return;
    __stcs(&g_sedge[pos], make_int2(col, e));
}

// ---------------- fused score + softmax: warp per row ----------------
// Coalesced lane mapping: lane (h,l) handles channel float4s {l, l+8, l+16, l+24}
// of head h -> every x LDG.128 touches exactly ONE 128B line (nL=1), 4x fewer
// L1tex wavefronts than the previous l*4+k mapping.
__global__ void score_kernel(const float* __restrict__ x, float* __restrict__ out) {
    __shared__ float ssm[8][SMAX * 4];   // per-warp exp-score staging
    __shared__ int2  sedg[8][SMAX];      // per-warp edge staging
    int wid = threadIdx.x >> 5;
    int row = (blockIdx.x * blockDim.x + threadIdx.x) >> 5;
    int lane = threadIdx.x & 31;
    if (row >= NN) return;
    int cnt = g_cnt[row];
    if (cnt == 0) return;
    int beg = g_start[row];
    bool use_sm = (cnt <= SMAX);

    int h = lane >> 3;                 // head 0..3
    int l = lane & 7;                  // sublane 0..7

    // q_k = z[h*32 + l + 8k]  (pairs with x float4 index l + 8k)
    const float4* zr = (const float4*)(g_z + (size_t)row * ZC) + h * 32 + l;
    float4 q0 = __ldcs(zr + 0),  q1 = __ldcs(zr + 8);
    float4 q2 = __ldcs(zr + 16), q3 = __ldcs(zr + 24);

    if (use_sm) {
        for (int k = lane; k < cnt; k += 32) sedg[wid][k] = __ldcs(&g_sedge[beg + k]);
    }
    __syncwarp();

    float sum = 0.0f;                  // valid at l==0 (per-head partial)
    int j = 0;

    if (use_sm) {
        for (; j + 4 <= cnt; j += 4) {
            int c0 = sedg[wid][j].x,     c1 = sedg[wid][j + 1].x;
            int c2 = sedg[wid][j + 2].x, c3 = sedg[wid][j + 3].x;
            const float4* x0 = (const float4*)(x + (size_t)c0 * FF) + l;
            const float4* x1 = (const float4*)(x + (size_t)c1 * FF) + l;
            const float4* x2 = (const float4*)(x + (size_t)c2 * FF) + l;
            const float4* x3 = (const float4*)(x + (size_t)c3 * FF) + l;
            float4 a0 = x0[0], a1 = x0[8], a2 = x0[16], a3 = x0[24];
            float4 b0 = x1[0], b1 = x1[8], b2 = x1[16], b3 = x1[24];
            float4 d0 = x2[0], d1 = x2[8], d2 = x2[16], d3 = x2[24];
            float4 e0 = x3[0], e1 = x3[8], e2 = x3[16], e3 = x3[24];
            float s0 = q0.x*a0.x + q0.y*a0.y + q0.z*a0.z + q0.w*a0.w
                     + q1.x*a1.x + q1.y*a1.y + q1.z*a1.z + q1.w*a1.w
                     + q2.x*a2.x + q2.y*a2.y + q2.z*a2.z + q2.w*a2.w
                     + q3.x*a3.x + q3.y*a3.y + q3.z*a3.z + q3.w*a3.w;
            float s1 = q0.x*b0.x + q0.y*b0.y + q0.z*b0.z + q0.w*b0.w
                     + q1.x*b1.x + q1.y*b1.y + q1.z*b1.z + q1.w*b1.w
                     + q2.x*b2.x + q2.y*b2.y + q2.z*b2.z + q2.w*b2.w
                     + q3.x*b3.x + q3.y*b3.y + q3.z*b3.z + q3.w*b3.w;
            float s2 = q0.x*d0.x + q0.y*d0.y + q0.z*d0.z + q0.w*d0.w
                     + q1.x*d1.x + q1.y*d1.y + q1.z*d1.z + q1.w*d1.w
                     + q2.x*d2.x + q2.y*d2.y + q2.z*d2.z + q2.w*d2.w
                     + q3.x*d3.x + q3.y*d3.y + q3.z*d3.z + q3.w*d3.w;
            float s3 = q0.x*e0.x + q0.y*e0.y + q0.z*e0.z + q0.w*e0.w
                     + q1.x*e1.x + q1.y*e1.y + q1.z*e1.z + q1.w*e1.w
                     + q2.x*e2.x + q2.y*e2.y + q2.z*e2.z + q2.w*e2.w
                     + q3.x*e3.x + q3.y*e3.y + q3.z*e3.z + q3.w*e3.w;
            #pragma unroll
            for (int o = 1; o <= 4; o <<= 1) {
                s0 += __shfl_xor_sync(0xffffffffu, s0, o);
                s1 += __shfl_xor_sync(0xffffffffu, s1, o);
                s2 += __shfl_xor_sync(0xffffffffu, s2, o);
                s3 += __shfl_xor_sync(0xffffffffu, s3, o);
            }
            if (l == 0) {
                float ex0 = __expf(s0), ex1 = __expf(s1);
                float ex2 = __expf(s2), ex3 = __expf(s3);
                ssm[wid][(j + 0) * 4 + h] = ex0;
                ssm[wid][(j + 1) * 4 + h] = ex1;
                ssm[wid][(j + 2) * 4 + h] = ex2;
                ssm[wid][(j + 3) * 4 + h] = ex3;
                sum += (ex0 + ex1) + (ex2 + ex3);
            }
        }
        for (; j < cnt; j++) {
            int c0 = sedg[wid][j].x;
            const float4* x0 = (const float4*)(x + (size_t)c0 * FF) + l;
            float4 a0 = x0[0], a1 = x0[8], a2 = x0[16], a3 = x0[24];
            float s0 = q0.x*a0.x + q0.y*a0.y + q0.z*a0.z + q0.w*a0.w
                     + q1.x*a1.x + q1.y*a1.y + q1.z*a1.z + q1.w*a1.w
                     + q2.x*a2.x + q2.y*a2.y + q2.z*a2.z + q2.w*a2.w
                     + q3.x*a3.x + q3.y*a3.y + q3.z*a3.z + q3.w*a3.w;
            #pragma unroll
            for (int o = 1; o <= 4; o <<= 1) s0 += __shfl_xor_sync(0xffffffffu, s0, o);
            if (l == 0) {
                float ex0 = __expf(s0);
                ssm[wid][j * 4 + h] = ex0;
                sum += ex0;
            }
        }
    } else {
        // rare fallback: global sedge + global ssc (exact, unoptimized)
        for (; j < cnt; j++) {
            int2 se = __ldcs(&g_sedge[beg + j]);
            const float4* x0 = (const float4*)(x + (size_t)se.x * FF) + l;
            float4 a0 = x0[0], a1 = x0[8], a2 = x0[16], a3 = x0[24];
            float s0 = q0.x*a0.x + q0.y*a0.y + q0.z*a0.z + q0.w*a0.w
                     + q1.x*a1.x + q1.y*a1.y + q1.z*a1.z + q1.w*a1.w
                     + q2.x*a2.x + q2.y*a2.y + q2.z*a2.z + q2.w*a2.w
                     + q3.x*a3.x + q3.y*a3.y + q3.z*a3.z + q3.w*a3.w;
            #pragma unroll
            for (int o = 1; o <= 4; o <<= 1) s0 += __shfl_xor_sync(0xffffffffu, s0, o);
            if (l == 0) {
                float ex0 = __expf(s0);
                g_ssc[(size_t)(beg + j) * HH + h] = ex0;
                sum += ex0;
            }
        }
    }
    __syncwarp();

    float sm0 = __shfl_sync(0xffffffffu, sum, 0);
    float sm1 = __shfl_sync(0xffffffffu, sum, 8);
    float sm2 = __shfl_sync(0xffffffffu, sum, 16);
    float sm3 = __shfl_sync(0xffffffffu, sum, 24);
    float i0 = 1.0f / sm0, i1 = 1.0f / sm1, i2 = 1.0f / sm2, i3 = 1.0f / sm3;

    // pass 2: normalize + head-mean; scatter with evict-first stores
    if (use_sm) {
        for (int k = lane; k < cnt; k += 32) {
            float4 e = *(const float4*)&ssm[wid][k * 4];
            int orig = sedg[wid][k].y;
            __stcs(&out[orig], 0.25f * (e.x * i0 + e.y * i1 + e.z * i2 + e.w * i3));
        }
    } else {
        for (int k = lane; k < cnt; k += 32) {
            float4 e = *(const float4*)(g_ssc + (size_t)(beg + k) * HH);
            int2 se = __ldcs(&g_sedge[beg + k]);
            __stcs(&out[se.y], 0.25f * (e.x * i0 + e.y * i1 + e.z * i2 + e.w * i3));
        }
    }
}

// ---------------- launch ----------------
extern "C" void kernel_launch(void* const* d_in, const int* in_sizes, int n_in,
                              void* d_out, int out_size) {
    const float* x    = nullptr;
    const float* W    = nullptr;
    const float* bias = nullptr;
    const void*  ei   = nullptr;
    for (int i = 0; i < n_in; i++) {
        long long sz = in_sizes[i];
        if      (sz == (long long)NN * FF)  x    = (const float*)d_in[i];
        else if (sz == (long long)QKC * FF) W    = (const float*)d_in[i];
        else if (sz == (long long)QKC)      bias = (const float*)d_in[i];
        else if (sz == 2LL * EE)            ei   = d_in[i];
    }
    if (!x)    x    = (const float*)d_in[0];
    if (!W)    W    = (const float*)d_in[1];
    if (!bias) bias = (const float*)d_in[2];
    if (!ei)   ei   = d_in[3];
    float* out = (float*)d_out;

    detect_kernel<<<1, 1024>>>(ei);                      // 1
    mcat_kernel<<<dim3(2, 2, 4), 256>>>(W);              // 2
    u_kernel<<<2, 256>>>(W, bias);                       // 3

    dim3 zgrid((NN + BM - 1) / BM, ZC / BN);
    zgemm_kernel<<<zgrid, 256>>>(x);                     // 4 <- ncu capture slot

    init_kernel<<<(NBINS + 255) / 256, 256>>>();         // 5
    hist_kernel<<<(EE + 255) / 256, 256>>>(ei);          // 6
    scan1_kernel<<<NB2, 1024>>>();
    scan2_kernel<<<1, 128>>>();
    scan3_kernel<<<(NBINS + 255) / 256, 256>>>();
    scatter_kernel<<<(EE + 255) / 256, 256>>>(ei);

    score_kernel<<<((size_t)NN * 32 + 255) / 256, 256>>>(x, out);
}